// round 4
// baseline (speedup 1.0000x reference)
#include <cuda_runtime.h>

// SpatialTransformer: trilinear interpolation of vol at absolute coords trf.
// vol: [B=2, D=160, H=192, W=160, C=1] float32
// trf: [B=2, D,H,W, 3] float32 absolute sample coords (z,y,x order = D,H,W)
// out: [B=2, D,H,W, 1] float32
//
// Each thread handles the SAME spatial point in both batches (i and i+PB):
// trf reads stay perfectly coalesced, and the thread holds 16 independent
// gather LDGs in flight for latency hiding against ~250-cyc L2 hits.
// All state is scalar (no arrays/structs) so ptxas keeps everything in
// registers and can front-batch the gather LDGs.

#define DD 160
#define HH 192
#define WW 160
#define PB (DD * HH * WW)       // 4,915,200 points per batch
#define NTOT (2 * PB)           // 9,830,400

__global__ __launch_bounds__(256)
void st_trilinear_kernel(const float* __restrict__ vol,
                         const float* __restrict__ trf,
                         float* __restrict__ out) {
    int i = blockIdx.x * blockDim.x + threadIdx.x;   // spatial point in batch 0
    if (i >= PB) return;

    const float MD = (float)(DD - 1);
    const float MH = (float)(HH - 1);
    const float MW = (float)(WW - 1);

    // 32-bit indexing throughout (3 * NTOT = 29.5M < 2^31).
    int tiA = 3 * i;
    int tiB = tiA + 3 * PB;

    float zA = __ldg(trf + tiA + 0);
    float yA = __ldg(trf + tiA + 1);
    float xA = __ldg(trf + tiA + 2);
    float zB = __ldg(trf + tiB + 0);
    float yB = __ldg(trf + tiB + 1);
    float xB = __ldg(trf + tiB + 2);

    // ---- weights & indices, point A ----------------------------------
    // Reference semantics:
    //   clipped = clip(loc, 0, max)
    //   l0 = clip(floor(loc), 0, max); l1 = clip(l0+1, 0, max)
    //   w_bit0 = l1 - clipped (pairs with l0); w_bit1 = 1 - w_bit0 (pairs with l1)
    float czA  = fminf(fmaxf(zA, 0.f), MD);
    float z0fA = fminf(fmaxf(floorf(zA), 0.f), MD);
    float z1fA = fminf(z0fA + 1.f, MD);
    float wz0A = z1fA - czA, wz1A = 1.f - wz0A;

    float cyA  = fminf(fmaxf(yA, 0.f), MH);
    float y0fA = fminf(fmaxf(floorf(yA), 0.f), MH);
    float y1fA = fminf(y0fA + 1.f, MH);
    float wy0A = y1fA - cyA, wy1A = 1.f - wy0A;

    float cxA  = fminf(fmaxf(xA, 0.f), MW);
    float x0fA = fminf(fmaxf(floorf(xA), 0.f), MW);
    float x1fA = fminf(x0fA + 1.f, MW);
    float wx0A = x1fA - cxA, wx1A = 1.f - wx0A;

    int iz0A = (int)z0fA, iz1A = (int)z1fA;
    int iy0A = (int)y0fA, iy1A = (int)y1fA;
    int ix0A = (int)x0fA, ix1A = (int)x1fA;

    int rA00 = iz0A * (HH * WW) + iy0A * WW;
    int rA01 = iz0A * (HH * WW) + iy1A * WW;
    int rA10 = iz1A * (HH * WW) + iy0A * WW;
    int rA11 = iz1A * (HH * WW) + iy1A * WW;

    // ---- weights & indices, point B (batch 1) ------------------------
    float czB  = fminf(fmaxf(zB, 0.f), MD);
    float z0fB = fminf(fmaxf(floorf(zB), 0.f), MD);
    float z1fB = fminf(z0fB + 1.f, MD);
    float wz0B = z1fB - czB, wz1B = 1.f - wz0B;

    float cyB  = fminf(fmaxf(yB, 0.f), MH);
    float y0fB = fminf(fmaxf(floorf(yB), 0.f), MH);
    float y1fB = fminf(y0fB + 1.f, MH);
    float wy0B = y1fB - cyB, wy1B = 1.f - wy0B;

    float cxB  = fminf(fmaxf(xB, 0.f), MW);
    float x0fB = fminf(fmaxf(floorf(xB), 0.f), MW);
    float x1fB = fminf(x0fB + 1.f, MW);
    float wx0B = x1fB - cxB, wx1B = 1.f - wx0B;

    int iz0B = (int)z0fB, iz1B = (int)z1fB;
    int iy0B = (int)y0fB, iy1B = (int)y1fB;
    int ix0B = (int)x0fB, ix1B = (int)x1fB;

    int base1 = PB;  // batch 1 volume offset
    int rB00 = base1 + iz0B * (HH * WW) + iy0B * WW;
    int rB01 = base1 + iz0B * (HH * WW) + iy1B * WW;
    int rB10 = base1 + iz1B * (HH * WW) + iy0B * WW;
    int rB11 = base1 + iz1B * (HH * WW) + iy1B * WW;

    // ---- 16 independent gathers, issued back-to-back -----------------
    float a000 = __ldg(vol + rA00 + ix0A);
    float a001 = __ldg(vol + rA00 + ix1A);
    float a010 = __ldg(vol + rA01 + ix0A);
    float a011 = __ldg(vol + rA01 + ix1A);
    float a100 = __ldg(vol + rA10 + ix0A);
    float a101 = __ldg(vol + rA10 + ix1A);
    float a110 = __ldg(vol + rA11 + ix0A);
    float a111 = __ldg(vol + rA11 + ix1A);

    float b000 = __ldg(vol + rB00 + ix0B);
    float b001 = __ldg(vol + rB00 + ix1B);
    float b010 = __ldg(vol + rB01 + ix0B);
    float b011 = __ldg(vol + rB01 + ix1B);
    float b100 = __ldg(vol + rB10 + ix0B);
    float b101 = __ldg(vol + rB10 + ix1B);
    float b110 = __ldg(vol + rB11 + ix0B);
    float b111 = __ldg(vol + rB11 + ix1B);

    // ---- reduce ------------------------------------------------------
    float sA00 = fmaf(wx0A, a000, wx1A * a001);
    float sA01 = fmaf(wx0A, a010, wx1A * a011);
    float sA10 = fmaf(wx0A, a100, wx1A * a101);
    float sA11 = fmaf(wx0A, a110, wx1A * a111);
    float szA0 = fmaf(wy0A, sA00, wy1A * sA01);
    float szA1 = fmaf(wy0A, sA10, wy1A * sA11);
    float oA   = fmaf(wz0A, szA0, wz1A * szA1);

    float sB00 = fmaf(wx0B, b000, wx1B * b001);
    float sB01 = fmaf(wx0B, b010, wx1B * b011);
    float sB10 = fmaf(wx0B, b100, wx1B * b101);
    float sB11 = fmaf(wx0B, b110, wx1B * b111);
    float szB0 = fmaf(wy0B, sB00, wy1B * sB01);
    float szB1 = fmaf(wy0B, sB10, wy1B * sB11);
    float oB   = fmaf(wz0B, szB0, wz1B * szB1);

    out[i]      = oA;
    out[i + PB] = oB;
}

extern "C" void kernel_launch(void* const* d_in, const int* in_sizes, int n_in,
                              void* d_out, int out_size) {
    // Expected metadata order: d_in[0] = vol (9,830,400 elems),
    // d_in[1] = trf (29,491,200 elems = 3x vol). Resolve defensively by size
    // so a swapped metadata order can't silently produce garbage.
    const float* vol = (const float*)d_in[0];
    const float* trf = (const float*)d_in[1];
    if (n_in >= 2 && in_sizes[0] > in_sizes[1]) {
        vol = (const float*)d_in[1];
        trf = (const float*)d_in[0];
    }
    float* out = (float*)d_out;

    int threads = 256;
    int blocks = (PB + threads - 1) / threads;
    st_trilinear_kernel<<<blocks, threads>>>(vol, trf, out);
}

// round 8
// speedup vs baseline: 1.1490x; 1.1490x over previous
#include <cuda_runtime.h>

// SpatialTransformer: trilinear interpolation of vol at absolute coords trf.
// vol: [B=2, D=160, H=192, W=160, C=1] float32
// trf: [B=2, D,H,W, 3] float32 absolute coords (z,y,x = D,H,W)
// out: [B=2, D,H,W, 1] float32
//
// R4 insight (ncu): kernel is L1tex-WAVEFRONT bound (90.1%), not L2/DRAM.
// Every gather LDG costs a wavefront per distinct line per lane, hit or miss.
// Fix: fetch each row's x-neighborhood with ONE aligned LDG.128 (row bases are
// 640B-aligned, so (r + (ix0&~3)) is 16B-aligned), plus a 1/4-probability
// predicated scalar for the straddle case (ix0%4==3, not clamped).
// 8 gathers/point -> 4 + ~1. Pair-interp + SEL-chain avoids dynamic float4
// indexing (no local-mem spill).

#define DD 160
#define HH 192
#define WW 160
#define PB (DD * HH * WW)       // 4,915,200 points per batch

// Interp along x inside a float4 neighborhood.
// q covers vol[r+b .. r+b+3], e = vol[r+b+4] (valid iff k1==4, else 0).
// k1 = ix1 - b in {1,2,3,4}. Select pair-interp p[k1-1].
// Clamp case (ix1==ix0==b+3 -> k1==3): wx0==0 so p23 = q.w, correct.
__device__ __forceinline__ float xsel(float4 q, float e, float wx0, float wx1, int k1) {
    float p01 = fmaf(wx0, q.x, wx1 * q.y);
    float p12 = fmaf(wx0, q.y, wx1 * q.z);
    float p23 = fmaf(wx0, q.z, wx1 * q.w);
    float p34 = fmaf(wx0, q.w, wx1 * e);
    float r = (k1 == 1) ? p01 : (k1 == 2) ? p12 : (k1 == 3) ? p23 : p34;
    return r;
}

__global__ __launch_bounds__(256)
void st_trilinear_kernel(const float* __restrict__ vol,
                         const float* __restrict__ trf,
                         float* __restrict__ out) {
    int i = blockIdx.x * blockDim.x + threadIdx.x;   // spatial point in batch 0
    if (i >= PB) return;

    const float MD = (float)(DD - 1);
    const float MH = (float)(HH - 1);
    const float MW = (float)(WW - 1);

    int tiA = 3 * i;
    int tiB = tiA + 3 * PB;

    float zA = __ldg(trf + tiA + 0);
    float yA = __ldg(trf + tiA + 1);
    float xA = __ldg(trf + tiA + 2);
    float zB = __ldg(trf + tiB + 0);
    float yB = __ldg(trf + tiB + 1);
    float xB = __ldg(trf + tiB + 2);

    // ---- weights & indices (reference semantics) ---------------------
    // clipped = clip(loc,0,max); l0 = clip(floor(loc),0,max); l1 = clip(l0+1,0,max)
    // w0 = l1 - clipped (pairs with l0); w1 = 1 - w0 (pairs with l1)
    float czA  = fminf(fmaxf(zA, 0.f), MD);
    float z0fA = fminf(fmaxf(floorf(zA), 0.f), MD);
    float z1fA = fminf(z0fA + 1.f, MD);
    float wz0A = z1fA - czA, wz1A = 1.f - wz0A;

    float cyA  = fminf(fmaxf(yA, 0.f), MH);
    float y0fA = fminf(fmaxf(floorf(yA), 0.f), MH);
    float y1fA = fminf(y0fA + 1.f, MH);
    float wy0A = y1fA - cyA, wy1A = 1.f - wy0A;

    float cxA  = fminf(fmaxf(xA, 0.f), MW);
    float x0fA = fminf(fmaxf(floorf(xA), 0.f), MW);
    float x1fA = fminf(x0fA + 1.f, MW);
    float wx0A = x1fA - cxA, wx1A = 1.f - wx0A;

    int iz0A = (int)z0fA, iz1A = (int)z1fA;
    int iy0A = (int)y0fA, iy1A = (int)y1fA;
    int ix0A = (int)x0fA, ix1A = (int)x1fA;
    int bA   = ix0A & ~3;          // 16B-aligned float4 base within row
    int k1A  = ix1A - bA;          // in {1,2,3,4}

    int rA00 = iz0A * (HH * WW) + iy0A * WW;
    int rA01 = iz0A * (HH * WW) + iy1A * WW;
    int rA10 = iz1A * (HH * WW) + iy0A * WW;
    int rA11 = iz1A * (HH * WW) + iy1A * WW;

    float czB  = fminf(fmaxf(zB, 0.f), MD);
    float z0fB = fminf(fmaxf(floorf(zB), 0.f), MD);
    float z1fB = fminf(z0fB + 1.f, MD);
    float wz0B = z1fB - czB, wz1B = 1.f - wz0B;

    float cyB  = fminf(fmaxf(yB, 0.f), MH);
    float y0fB = fminf(fmaxf(floorf(yB), 0.f), MH);
    float y1fB = fminf(y0fB + 1.f, MH);
    float wy0B = y1fB - cyB, wy1B = 1.f - wy0B;

    float cxB  = fminf(fmaxf(xB, 0.f), MW);
    float x0fB = fminf(fmaxf(floorf(xB), 0.f), MW);
    float x1fB = fminf(x0fB + 1.f, MW);
    float wx0B = x1fB - cxB, wx1B = 1.f - wx0B;

    int iz0B = (int)z0fB, iz1B = (int)z1fB;
    int iy0B = (int)y0fB, iy1B = (int)y1fB;
    int ix0B = (int)x0fB, ix1B = (int)x1fB;
    int bB   = ix0B & ~3;
    int k1B  = ix1B - bB;

    int rB00 = PB + iz0B * (HH * WW) + iy0B * WW;
    int rB01 = PB + iz0B * (HH * WW) + iy1B * WW;
    int rB10 = PB + iz1B * (HH * WW) + iy0B * WW;
    int rB11 = PB + iz1B * (HH * WW) + iy1B * WW;

    // ---- 8 aligned float4 gathers, back-to-back ----------------------
    const float4* __restrict__ v4 = reinterpret_cast<const float4*>(vol);
    float4 qA00 = __ldg(v4 + ((rA00 + bA) >> 2));
    float4 qA01 = __ldg(v4 + ((rA01 + bA) >> 2));
    float4 qA10 = __ldg(v4 + ((rA10 + bA) >> 2));
    float4 qA11 = __ldg(v4 + ((rA11 + bA) >> 2));
    float4 qB00 = __ldg(v4 + ((rB00 + bB) >> 2));
    float4 qB01 = __ldg(v4 + ((rB01 + bB) >> 2));
    float4 qB10 = __ldg(v4 + ((rB10 + bB) >> 2));
    float4 qB11 = __ldg(v4 + ((rB11 + bB) >> 2));

    // ---- straddle extras, predicated loads (no divergence envelope) ---
    // Active for ~1/4 of lanes; address in-bounds whenever k1==4
    // (then ix1 = b+4 <= 159).
    bool sA = (k1A == 4), sB = (k1B == 4);
    float eA00 = sA ? __ldg(vol + rA00 + bA + 4) : 0.f;
    float eA01 = sA ? __ldg(vol + rA01 + bA + 4) : 0.f;
    float eA10 = sA ? __ldg(vol + rA10 + bA + 4) : 0.f;
    float eA11 = sA ? __ldg(vol + rA11 + bA + 4) : 0.f;
    float eB00 = sB ? __ldg(vol + rB00 + bB + 4) : 0.f;
    float eB01 = sB ? __ldg(vol + rB01 + bB + 4) : 0.f;
    float eB10 = sB ? __ldg(vol + rB10 + bB + 4) : 0.f;
    float eB11 = sB ? __ldg(vol + rB11 + bB + 4) : 0.f;

    // ---- reduce ------------------------------------------------------
    float sA00 = xsel(qA00, eA00, wx0A, wx1A, k1A);
    float sA01 = xsel(qA01, eA01, wx0A, wx1A, k1A);
    float sA10 = xsel(qA10, eA10, wx0A, wx1A, k1A);
    float sA11 = xsel(qA11, eA11, wx0A, wx1A, k1A);
    float szA0 = fmaf(wy0A, sA00, wy1A * sA01);
    float szA1 = fmaf(wy0A, sA10, wy1A * sA11);
    float oA   = fmaf(wz0A, szA0, wz1A * szA1);

    float sB00 = xsel(qB00, eB00, wx0B, wx1B, k1B);
    float sB01 = xsel(qB01, eB01, wx0B, wx1B, k1B);
    float sB10 = xsel(qB10, eB10, wx0B, wx1B, k1B);
    float sB11 = xsel(qB11, eB11, wx0B, wx1B, k1B);
    float szB0 = fmaf(wy0B, sB00, wy1B * sB01);
    float szB1 = fmaf(wy0B, sB10, wy1B * sB11);
    float oB   = fmaf(wz0B, szB0, wz1B * szB1);

    out[i]      = oA;
    out[i + PB] = oB;
}

extern "C" void kernel_launch(void* const* d_in, const int* in_sizes, int n_in,
                              void* d_out, int out_size) {
    // Expected order: d_in[0] = vol (9,830,400), d_in[1] = trf (3x). Resolve
    // defensively by size so a swapped metadata order can't silently break.
    const float* vol = (const float*)d_in[0];
    const float* trf = (const float*)d_in[1];
    if (n_in >= 2 && in_sizes[0] > in_sizes[1]) {
        vol = (const float*)d_in[1];
        trf = (const float*)d_in[0];
    }
    float* out = (float*)d_out;

    int threads = 256;
    int blocks = (PB + threads - 1) / threads;
    st_trilinear_kernel<<<blocks, threads>>>(vol, trf, out);
}

// round 9
// speedup vs baseline: 1.1515x; 1.0022x over previous
#include <cuda_runtime.h>

// SpatialTransformer: trilinear interpolation of vol at absolute coords trf.
// vol: [B=2, D=160, H=192, W=160, C=1] float32
// trf: [B=2, D,H,W, 3] float32 absolute coords (z,y,x = D,H,W)
// out: [B=2, D,H,W, 1] float32
//
// R4 (scalar, 205.6us): L1tex-wavefront bound (90.1%), occ 91%.
// R8 (float4 collapse, 2pt/thread, 178.9us): L1 86.5% still binder, but
// regs=64 crushed occupancy to 42%. Wavefronts/point are ~25% above the
// 4-line floor; the remaining lever is occupancy.
// R9: same float4+predicated-extra load scheme, ONE point per thread ->
// regs ~40, occupancy ~75%, keep L1tex saturated with 2x warps.

#define DD 160
#define HH 192
#define WW 160
#define PB (DD * HH * WW)       // 4,915,200 points per batch
#define NTOT (2 * PB)           // 9,830,400

// Interp along x inside a float4 neighborhood.
// q covers vol[r+b .. r+b+3], e = vol[r+b+4] (valid iff k1==4, else 0).
// k1 = ix1 - b in {1,2,3,4}. Select pair-interp p[k1-1].
// Clamp case (ix1==ix0==b+3 -> k1==3): wx0==0 so p23 = q.w, correct.
__device__ __forceinline__ float xsel(float4 q, float e, float wx0, float wx1, int k1) {
    float p01 = fmaf(wx0, q.x, wx1 * q.y);
    float p12 = fmaf(wx0, q.y, wx1 * q.z);
    float p23 = fmaf(wx0, q.z, wx1 * q.w);
    float p34 = fmaf(wx0, q.w, wx1 * e);
    float r = (k1 == 1) ? p01 : (k1 == 2) ? p12 : (k1 == 3) ? p23 : p34;
    return r;
}

__global__ __launch_bounds__(256)
void st_trilinear_kernel(const float* __restrict__ vol,
                         const float* __restrict__ trf,
                         float* __restrict__ out) {
    int i = blockIdx.x * blockDim.x + threadIdx.x;
    if (i >= NTOT) return;

    const float MD = (float)(DD - 1);
    const float MH = (float)(HH - 1);
    const float MW = (float)(WW - 1);

    // batch volume offset without integer divide
    int voff = (i >= PB) ? PB : 0;

    int ti = 3 * i;   // 3*NTOT = 29.5M < 2^31
    float z = __ldg(trf + ti + 0);
    float y = __ldg(trf + ti + 1);
    float x = __ldg(trf + ti + 2);

    // ---- weights & indices (reference semantics) ---------------------
    // clipped = clip(loc,0,max); l0 = clip(floor(loc),0,max); l1 = clip(l0+1,0,max)
    // w0 = l1 - clipped (pairs with l0); w1 = 1 - w0 (pairs with l1)
    float cz  = fminf(fmaxf(z, 0.f), MD);
    float z0f = fminf(fmaxf(floorf(z), 0.f), MD);
    float z1f = fminf(z0f + 1.f, MD);
    float wz0 = z1f - cz, wz1 = 1.f - wz0;

    float cy  = fminf(fmaxf(y, 0.f), MH);
    float y0f = fminf(fmaxf(floorf(y), 0.f), MH);
    float y1f = fminf(y0f + 1.f, MH);
    float wy0 = y1f - cy, wy1 = 1.f - wy0;

    float cx  = fminf(fmaxf(x, 0.f), MW);
    float x0f = fminf(fmaxf(floorf(x), 0.f), MW);
    float x1f = fminf(x0f + 1.f, MW);
    float wx0 = x1f - cx, wx1 = 1.f - wx0;

    int iz0 = (int)z0f, iz1 = (int)z1f;
    int iy0 = (int)y0f, iy1 = (int)y1f;
    int ix0 = (int)x0f, ix1 = (int)x1f;
    int b   = ix0 & ~3;           // 16B-aligned float4 base within row
    int k1  = ix1 - b;            // in {1,2,3,4}

    int r00 = voff + iz0 * (HH * WW) + iy0 * WW;
    int r01 = voff + iz0 * (HH * WW) + iy1 * WW;
    int r10 = voff + iz1 * (HH * WW) + iy0 * WW;
    int r11 = voff + iz1 * (HH * WW) + iy1 * WW;

    // ---- 4 aligned float4 gathers, back-to-back ----------------------
    const float4* __restrict__ v4 = reinterpret_cast<const float4*>(vol);
    float4 q00 = __ldg(v4 + ((r00 + b) >> 2));
    float4 q01 = __ldg(v4 + ((r01 + b) >> 2));
    float4 q10 = __ldg(v4 + ((r10 + b) >> 2));
    float4 q11 = __ldg(v4 + ((r11 + b) >> 2));

    // ---- straddle extras, predicated (active ~1/4 of lanes) ----------
    // In-bounds whenever k1==4 (then ix1 = b+4 <= 159).
    bool s = (k1 == 4);
    float e00 = s ? __ldg(vol + r00 + b + 4) : 0.f;
    float e01 = s ? __ldg(vol + r01 + b + 4) : 0.f;
    float e10 = s ? __ldg(vol + r10 + b + 4) : 0.f;
    float e11 = s ? __ldg(vol + r11 + b + 4) : 0.f;

    // ---- reduce ------------------------------------------------------
    float s00 = xsel(q00, e00, wx0, wx1, k1);
    float s01 = xsel(q01, e01, wx0, wx1, k1);
    float s10 = xsel(q10, e10, wx0, wx1, k1);
    float s11 = xsel(q11, e11, wx0, wx1, k1);

    float sz0 = fmaf(wy0, s00, wy1 * s01);
    float sz1 = fmaf(wy0, s10, wy1 * s11);
    out[i]    = fmaf(wz0, sz0, wz1 * sz1);
}

extern "C" void kernel_launch(void* const* d_in, const int* in_sizes, int n_in,
                              void* d_out, int out_size) {
    // Expected order: d_in[0] = vol (9,830,400), d_in[1] = trf (3x). Resolve
    // defensively by size so a swapped metadata order can't silently break.
    const float* vol = (const float*)d_in[0];
    const float* trf = (const float*)d_in[1];
    if (n_in >= 2 && in_sizes[0] > in_sizes[1]) {
        vol = (const float*)d_in[1];
        trf = (const float*)d_in[0];
    }
    float* out = (float*)d_out;

    int threads = 256;
    int blocks = (NTOT + threads - 1) / threads;
    st_trilinear_kernel<<<blocks, threads>>>(vol, trf, out);
}